// round 7
// baseline (speedup 1.0000x reference)
#include <cuda_runtime.h>
#include <math.h>

// Problem constants
#define BB 2
#define SS 2048
#define DD 1024
#define NH 16
#define NKV 4
#define DH 64
#define MM (BB*SS)   // 4096

// Permuted-row layout (4 groups of 16 floats at offsets 0,16,36,52; row stride 72)
#define PR 72
#define VTROW (32 * PR)

// ---------------- scratch ----------------
__device__ float g_q [MM * DD];
__device__ float g_k [MM * NKV*DH];
__device__ float g_v [MM * NKV*DH];
__device__ float g_qr[MM * DD];
__device__ float g_kr[BB*NKV*SS * PR];
__device__ float g_vt[BB*NKV*DH * VTROW];
__device__ float g_ao[MM * DD];
__device__ float g_mb[MM];

// ---------------- helpers ----------------
__device__ __forceinline__ float f2tf(float x) {
    unsigned u;
    asm("cvt.rna.tf32.f32 %0, %1;" : "=r"(u) : "f"(x));
    return __uint_as_float(u);
}

__device__ __forceinline__ void mma8(float* d, const unsigned* a, const unsigned* b,
                                     const float* c) {
    asm volatile(
        "mma.sync.aligned.m16n8k8.row.col.f32.tf32.tf32.f32 "
        "{%0,%1,%2,%3}, {%4,%5,%6,%7}, {%8,%9}, {%10,%11,%12,%13};"
        : "=f"(d[0]), "=f"(d[1]), "=f"(d[2]), "=f"(d[3])
        : "r"(a[0]), "r"(a[1]), "r"(a[2]), "r"(a[3]),
          "r"(b[0]), "r"(b[1]),
          "f"(c[0]), "f"(c[1]), "f"(c[2]), "f"(c[3]));
}

__device__ __forceinline__ unsigned sm_u32(const void* p) {
    unsigned a;
    asm("{ .reg .u64 t; cvta.to.shared.u64 t, %1; cvt.u32.u64 %0, t; }"
        : "=r"(a) : "l"(p));
    return a;
}
#define CPA16(d, s) asm volatile("cp.async.cg.shared.global [%0], [%1], 16;" :: "r"(d), "l"(s))
#define CPC()  asm volatile("cp.async.commit_group;")
#define CPW0() asm volatile("cp.async.wait_group 0;" ::: "memory")

// ---------------- tf32 GEMM body: ping-pong double-buffered ----------------
#define TBM 128
#define TBN 128
#define TBK 32
#define ASTR 36
#define BSTR 136
#define GSMEM ((2 * TBM * ASTR + 2 * TBK * BSTR) * 4)   // 70 KB

__device__ __forceinline__ void gemm_body(
    const float* __restrict__ A, const float* __restrict__ B,
    const float* __restrict__ bias, float* __restrict__ C,
    int N, int K, int bm, int bn, bool cvtOut, float* sm)
{
    float* As = sm;
    float* Bs = sm + 2 * TBM * ASTR;

    const int tid  = threadIdx.x;
    const int lane = tid & 31;
    const int warp = tid >> 5;
    const int gr   = lane >> 2;
    const int tig  = lane & 3;
    const int warp_m = (warp & 1) * 64;
    const int warp_n = (warp >> 1) * 32;

    float acc[4][4][4];
#pragma unroll
    for (int mt = 0; mt < 4; mt++)
#pragma unroll
        for (int nt = 0; nt < 4; nt++)
#pragma unroll
            for (int i = 0; i < 4; i++) acc[mt][nt][i] = 0.f;

    float4 ra[4], rb[4];

    auto ldg = [&](int t) {
        int k0 = t * TBK;
#pragma unroll
        for (int i = 0; i < 4; i++) {
            int idx = tid + i * 256;
            int m = idx >> 3, c = (idx & 7) << 2;
            ra[i] = *(const float4*)(A + (size_t)(bm + m) * K + k0 + c);
            int kk = idx >> 5, n = (idx & 31) << 2;
            rb[i] = *(const float4*)(B + (size_t)(k0 + kk) * N + bn + n);
        }
    };
    auto sts = [&](int bi) {
        float* Asb = As + bi * TBM * ASTR;
        float* Bsb = Bs + bi * TBK * BSTR;
#pragma unroll
        for (int i = 0; i < 4; i++) {
            int idx = tid + i * 256;
            int m = idx >> 3, c = (idx & 7) << 2;
            Asb[m * ASTR + c + 0] = f2tf(ra[i].x);
            Asb[m * ASTR + c + 1] = f2tf(ra[i].y);
            Asb[m * ASTR + c + 2] = f2tf(ra[i].z);
            Asb[m * ASTR + c + 3] = f2tf(ra[i].w);
            int kk = idx >> 5, n = (idx & 31) << 2;
            float4 t4 = make_float4(f2tf(rb[i].x), f2tf(rb[i].y),
                                    f2tf(rb[i].z), f2tf(rb[i].w));
            *(float4*)(&Bsb[kk * BSTR + n]) = t4;
        }
    };

    const int T = K / TBK;
    ldg(0);
    sts(0);
    __syncthreads();
    if (T > 1) ldg(1);

    for (int t = 0; t < T; t++) {
        if (t + 1 < T) sts((t + 1) & 1);
        if (t + 2 < T) ldg(t + 2);

        const float* Asb = As + (t & 1) * TBM * ASTR;
        const float* Bsb = Bs + (t & 1) * TBK * BSTR;
#pragma unroll
        for (int ks = 0; ks < 4; ks++) {
            int kk = ks * 8;
            unsigned afr[4][4], bfr[4][2];
#pragma unroll
            for (int mt = 0; mt < 4; mt++) {
                int r0 = warp_m + mt * 16 + gr;
                afr[mt][0] = __float_as_uint(Asb[r0 * ASTR + kk + tig]);
                afr[mt][1] = __float_as_uint(Asb[(r0 + 8) * ASTR + kk + tig]);
                afr[mt][2] = __float_as_uint(Asb[r0 * ASTR + kk + tig + 4]);
                afr[mt][3] = __float_as_uint(Asb[(r0 + 8) * ASTR + kk + tig + 4]);
            }
#pragma unroll
            for (int nt = 0; nt < 4; nt++) {
                int c0 = warp_n + nt * 8 + gr;
                bfr[nt][0] = __float_as_uint(Bsb[(kk + tig) * BSTR + c0]);
                bfr[nt][1] = __float_as_uint(Bsb[(kk + tig + 4) * BSTR + c0]);
            }
#pragma unroll
            for (int mt = 0; mt < 4; mt++)
#pragma unroll
                for (int nt = 0; nt < 4; nt++)
                    mma8(acc[mt][nt], afr[mt], bfr[nt], acc[mt][nt]);
        }
        __syncthreads();
    }

#pragma unroll
    for (int mt = 0; mt < 4; mt++) {
        int r0 = bm + warp_m + mt * 16 + gr;
#pragma unroll
        for (int nt = 0; nt < 4; nt++) {
            int c0 = bn + warp_n + nt * 8 + 2 * tig;
            float bx = bias[c0], by = bias[c0 + 1];
            float2 o0 = make_float2(acc[mt][nt][0] + bx, acc[mt][nt][1] + by);
            float2 o1 = make_float2(acc[mt][nt][2] + bx, acc[mt][nt][3] + by);
            if (cvtOut) {
                o0.x = f2tf(o0.x); o0.y = f2tf(o0.y);
                o1.x = f2tf(o1.x); o1.y = f2tf(o1.y);
            }
            *(float2*)(&C[(size_t)r0 * N + c0]) = o0;
            *(float2*)(&C[(size_t)(r0 + 8) * N + c0]) = o1;
        }
    }
}

// ---- merged Q/K/V projections: grid (12, 32) ----
__global__ __launch_bounds__(256)
void proj_all(const float* __restrict__ hs,
              const float* __restrict__ Wq, const float* __restrict__ bq,
              const float* __restrict__ Wk, const float* __restrict__ bk,
              const float* __restrict__ Wv, const float* __restrict__ bv,
              float* __restrict__ q, float* __restrict__ k, float* __restrict__ v)
{
    extern __shared__ float sm[];
    int bx = blockIdx.x;
    const float *B, *bias; float* C; int N, bn; bool cvt;
    if (bx < 8)       { B = Wq; bias = bq; C = q; N = DD;       bn = bx * TBN;        cvt = false; }
    else if (bx < 10) { B = Wk; bias = bk; C = k; N = NKV * DH; bn = (bx - 8) * TBN;  cvt = false; }
    else              { B = Wv; bias = bv; C = v; N = NKV * DH; bn = (bx - 10) * TBN; cvt = true;  }
    gemm_body(hs, B, bias, C, N, DD, blockIdx.y * TBM, bn, cvt, sm);
}

// ---- output projection ----
__global__ __launch_bounds__(256)
void tgemm_o(const float* __restrict__ A, const float* __restrict__ Wo,
             const float* __restrict__ bo, float* __restrict__ C)
{
    extern __shared__ float sm[];
    gemm_body(A, Wo, bo, C, DD, DD, blockIdx.y * TBM, blockIdx.x * TBN, false, sm);
}

// ---------------- rope + vtrans + mask bias, one launch ----------------
__global__ void post_kernel(const float* __restrict__ qin, float* __restrict__ qout,
                            const float* __restrict__ kin, float* __restrict__ kout,
                            const float* __restrict__ V, float* __restrict__ Vt,
                            const float* __restrict__ mask, float* __restrict__ mb)
{
    __shared__ float t[64 * 68];
    const int tid = threadIdx.x;

    if (blockIdx.x < 256) {
        // ---- vtrans part ----
        int bi = blockIdx.x;
        int kt  = bi & 31;
        int kvh = (bi >> 5) & 3;
        int b   = bi >> 7;
#pragma unroll
        for (int i = 0; i < 4; i++) {
            int f = tid + i * 256;
            int r = f >> 4, c = (f & 15) << 2;
            *(float4*)&t[r * 68 + c] =
                *(const float4*)(V + (size_t)(b * SS + kt * 64 + r) * (NKV * DH) + kvh * 64 + c);
        }
        __syncthreads();
        int d = tid >> 2;
        int g = tid & 3;
        int off = g * 16 + (g >> 1) * 4;
        float* out = Vt + ((size_t)(b * NKV + kvh) * DH + d) * VTROW + kt * PR + off;
#pragma unroll
        for (int j = 0; j < 4; j++) {
            float4 w;
            w.x = t[(4 * (4 * j + 0) + g) * 68 + d];
            w.y = t[(4 * (4 * j + 1) + g) * 68 + d];
            w.z = t[(4 * (4 * j + 2) + g) * 68 + d];
            w.w = t[(4 * (4 * j + 3) + g) * 68 + d];
            *(float4*)(out + 4 * j) = w;
        }
        return;
    }

    // ---- rope part ----
    int idx = (blockIdx.x - 256) * blockDim.x + tid;
    const int qTotal = MM * NH * 32;
    const int kTotal = MM * NKV * 32;
    if (idx >= qTotal + kTotal) {
        int i = idx - qTotal - kTotal;
        if (i < MM) mb[i] = (1.0f - mask[i]) * -1e9f;
        return;
    }
    bool isQ = idx < qTotal;
    int nHeads = isQ ? NH : NKV;
    float scale = isQ ? 0.125f : 1.0f;
    const float* in = isQ ? qin : kin;
    if (!isQ) idx -= qTotal;

    int i   = idx & 31;
    int h   = (idx >> 5) % nHeads;
    int row = idx / (nHeads * 32);
    int s   = row & (SS - 1);
    int b   = row >> 11;

    float ex  = -(float)(2 * i) / 64.0f;
    float inv = powf(10000.0f, ex);
    float ang = (float)s * inv;
    float sn, cs;
    sincosf(ang, &sn, &cs);

    const float* p = in + (size_t)row * (nHeads * 64) + h * 64;
    float x1 = p[i], x2 = p[i + 32];
    float y1 = f2tf((x1 * cs - x2 * sn) * scale);
    float y2 = f2tf((x1 * sn + x2 * cs) * scale);

    if (isQ) {
        float* q = qout + (size_t)row * (NH * 64) + h * 64;
        q[i] = y1; q[i + 32] = y2;
    } else {
        int g = i & 3;
        int off = g * 16 + (g >> 1) * 4;
        float* q = kout + ((size_t)(b * NKV + h) * SS + s) * PR;
        q[off + (i >> 2)]     = y1;
        q[off + (i >> 2) + 8] = y2;
    }
}

// ---------------- flash attention: 4 warps x 32 q-rows, 1 barrier/tile ------
#define BQ 128
#define STG (64 * PR * 2 + 64)                  // K + V + mask per stage
#define ATTN_SMEM ((2 * STG + BQ * PR) * 4)     // ~111 KB

__global__ __launch_bounds__(128, 2)
void attn_mma_kernel(const float* __restrict__ Q,    // roped+scaled+tf32, natural
                     const float* __restrict__ Kp,   // permuted K
                     const float* __restrict__ Vt,   // transposed+permuted V
                     const float* __restrict__ MB,   // mask bias
                     float* __restrict__ O)
{
    extern __shared__ float sm[];
    float* P = sm + 2 * STG;

    const int qb = blockIdx.x, h = blockIdx.y, b = blockIdx.z;
    const int kvh = h >> 2;
    const int tid  = threadIdx.x;
    const int lane = tid & 31;
    const int warp = tid >> 5;
    const int gr   = lane >> 2;
    const int tig  = lane & 3;
    const int q0   = warp * 32;
    const int goff = tig * 16 + (tig >> 1) * 4;

    const float* Kbase = Kp + (size_t)(b * NKV + kvh) * SS * PR;
    const float* Vbase = Vt + (size_t)(b * NKV + kvh) * DH * VTROW;

    auto issue = [&](int kt, int bi) {
        float* Ks = sm + bi * STG;
        float* Vs = Ks + 64 * PR;
        float* Ms = Vs + 64 * PR;
#pragma unroll
        for (int i = 0; i < 8; i++) {
            int idx = tid + i * 128;
            int r = idx >> 4, c = idx & 15;
            int g = c >> 2, j = c & 3;
            int fo = g * 16 + (g >> 1) * 4 + 4 * j;
            CPA16(sm_u32(&Ks[r * PR + fo]), Kbase + (size_t)(kt * 64 + r) * PR + fo);
            CPA16(sm_u32(&Vs[r * PR + fo]), Vbase + (size_t)r * VTROW + kt * PR + fo);
        }
        if (tid < 16)
            CPA16(sm_u32(&Ms[tid * 4]), MB + b * SS + kt * 64 + tid * 4);
        CPC();
    };

    issue(0, 0);   // overlap stage-0 fill with Q staging

    // stage Q tile (stride PR) and hoist fragments
#pragma unroll
    for (int i = 0; i < 16; i++) {
        int idx = tid + i * 128;
        int r = idx >> 4, c = (idx & 15) << 2;
        *(float4*)&P[r * PR + c] =
            *(const float4*)(Q + (size_t)(b * SS + qb * BQ + r) * DD + h * 64 + c);
    }
    __syncthreads();
    unsigned qa[2][8][4];
#pragma unroll
    for (int mt = 0; mt < 2; mt++)
#pragma unroll
        for (int ks = 0; ks < 8; ks++) {
            int r0 = q0 + mt * 16 + gr;
            qa[mt][ks][0] = __float_as_uint(P[r0 * PR + ks * 8 + tig]);
            qa[mt][ks][1] = __float_as_uint(P[(r0 + 8) * PR + ks * 8 + tig]);
            qa[mt][ks][2] = __float_as_uint(P[r0 * PR + ks * 8 + tig + 4]);
            qa[mt][ks][3] = __float_as_uint(P[(r0 + 8) * PR + ks * 8 + tig + 4]);
        }

    float o[2][8][4];
#pragma unroll
    for (int mt = 0; mt < 2; mt++)
#pragma unroll
        for (int nt = 0; nt < 8; nt++)
#pragma unroll
            for (int i = 0; i < 4; i++) o[mt][nt][i] = 0.f;
    float l[4] = {0.f, 0.f, 0.f, 0.f};

    const int NKT = SS / 64;
    for (int kt = 0; kt < NKT; kt++) {
        CPW0();
        __syncthreads();                 // stage kt visible; all warps past kt-1
        if (kt + 1 < NKT) issue(kt + 1, (kt + 1) & 1);

        float* Ks = sm + (kt & 1) * STG;
        float* Vs = Ks + 64 * PR;
        float* Ms = Vs + 64 * PR;

        // ---- S = Q @ K^T ----
        float s[2][8][4];
#pragma unroll
        for (int mt = 0; mt < 2; mt++)
#pragma unroll
            for (int nt = 0; nt < 8; nt++)
#pragma unroll
                for (int i = 0; i < 4; i++) s[mt][nt][i] = 0.f;

#pragma unroll
        for (int nt = 0; nt < 8; nt++) {
            const float* kb = Ks + (nt * 8 + gr) * PR + goff;
            float kr[16];
            *(float4*)(kr)      = *(const float4*)(kb);
            *(float4*)(kr + 4)  = *(const float4*)(kb + 4);
            *(float4*)(kr + 8)  = *(const float4*)(kb + 8);
            *(float4*)(kr + 12) = *(const float4*)(kb + 12);
#pragma unroll
            for (int ks = 0; ks < 8; ks++) {
                unsigned bfr[2] = { __float_as_uint(kr[2 * ks]),
                                    __float_as_uint(kr[2 * ks + 1]) };
                mma8(s[0][nt], qa[0][ks], bfr, s[0][nt]);
                mma8(s[1][nt], qa[1][ks], bfr, s[1][nt]);
            }
        }

        // ---- fixed-max softmax ----
#pragma unroll
        for (int mt = 0; mt < 2; mt++) {
            int r0 = q0 + mt * 16 + gr;
#pragma unroll
            for (int nt = 0; nt < 8; nt++) {
                int c0 = nt * 8 + 2 * tig;
                float mb0 = Ms[c0], mb1 = Ms[c0 + 1];
                float p00 = __expf(s[mt][nt][0] + mb0);
                float p01 = __expf(s[mt][nt][1] + mb1);
                float p10 = __expf(s[mt][nt][2] + mb0);
                float p11 = __expf(s[mt][nt][3] + mb1);
                l[mt * 2 + 0] += p00 + p01;
                l[mt * 2 + 1] += p10 + p11;
                int g0 = c0 & 3, g1 = (c0 + 1) & 3, pos = c0 >> 2;
                int off0 = g0 * 16 + (g0 >> 1) * 4 + pos;
                int off1 = g1 * 16 + (g1 >> 1) * 4 + pos;
                P[r0 * PR + off0] = p00;
                P[r0 * PR + off1] = p01;
                P[(r0 + 8) * PR + off0] = p10;
                P[(r0 + 8) * PR + off1] = p11;
            }
        }
        __syncwarp();

        // ---- P fragments ----
        float pr[2][2][16];
#pragma unroll
        for (int mt = 0; mt < 2; mt++)
#pragma unroll
            for (int rr = 0; rr < 2; rr++) {
                const float* pb = P + (q0 + mt * 16 + rr * 8 + gr) * PR + goff;
                *(float4*)(pr[mt][rr])      = *(const float4*)(pb);
                *(float4*)(pr[mt][rr] + 4)  = *(const float4*)(pb + 4);
                *(float4*)(pr[mt][rr] + 8)  = *(const float4*)(pb + 8);
                *(float4*)(pr[mt][rr] + 12) = *(const float4*)(pb + 12);
            }

        // ---- O += P @ V ----
#pragma unroll
        for (int nt = 0; nt < 8; nt++) {
            const float* vb = Vs + (nt * 8 + gr) * PR + goff;
            float vr[16];
            *(float4*)(vr)      = *(const float4*)(vb);
            *(float4*)(vr + 4)  = *(const float4*)(vb + 4);
            *(float4*)(vr + 8)  = *(const float4*)(vb + 8);
            *(float4*)(vr + 12) = *(const float4*)(vb + 12);
#pragma unroll
            for (int ks = 0; ks < 8; ks++) {
                unsigned bfr[2] = { __float_as_uint(vr[2 * ks]),
                                    __float_as_uint(vr[2 * ks + 1]) };
#pragma unroll
                for (int mt = 0; mt < 2; mt++) {
                    unsigned a[4] = { __float_as_uint(pr[mt][0][2 * ks]),
                                      __float_as_uint(pr[mt][1][2 * ks]),
                                      __float_as_uint(pr[mt][0][2 * ks + 1]),
                                      __float_as_uint(pr[mt][1][2 * ks + 1]) };
                    mma8(o[mt][nt], a, bfr, o[mt][nt]);
                }
            }
        }
    }

    // final l reduction
#pragma unroll
    for (int i = 0; i < 4; i++) {
        l[i] += __shfl_xor_sync(0xffffffffu, l[i], 1);
        l[i] += __shfl_xor_sync(0xffffffffu, l[i], 2);
    }

    // normalize + write
#pragma unroll
    for (int mt = 0; mt < 2; mt++) {
        float inv0 = 1.0f / l[mt * 2 + 0], inv1 = 1.0f / l[mt * 2 + 1];
        int rg = b * SS + qb * BQ + q0 + mt * 16 + gr;
#pragma unroll
        for (int nt = 0; nt < 8; nt++) {
            int col = h * 64 + nt * 8 + 2 * tig;
            *(float2*)(&O[(size_t)rg * DD + col]) =
                make_float2(o[mt][nt][0] * inv0, o[mt][nt][1] * inv0);
            *(float2*)(&O[(size_t)(rg + 8) * DD + col]) =
                make_float2(o[mt][nt][2] * inv1, o[mt][nt][3] * inv1);
        }
    }
}

// ---------------- launcher ----------------
extern "C" void kernel_launch(void* const* d_in, const int* in_sizes, int n_in,
                              void* d_out, int out_size)
{
    const float* hs   = (const float*)d_in[0];
    const float* mask = (const float*)d_in[1];
    const float* Wq   = (const float*)d_in[2];
    const float* bq   = (const float*)d_in[3];
    const float* Wk   = (const float*)d_in[4];
    const float* bk   = (const float*)d_in[5];
    const float* Wv   = (const float*)d_in[6];
    const float* bv   = (const float*)d_in[7];
    const float* Wo   = (const float*)d_in[8];
    const float* bo   = (const float*)d_in[9];
    float* out = (float*)d_out;

    float *q, *k, *v, *qr, *kr, *vt, *ao, *mb;
    cudaGetSymbolAddress((void**)&q,  g_q);
    cudaGetSymbolAddress((void**)&k,  g_k);
    cudaGetSymbolAddress((void**)&v,  g_v);
    cudaGetSymbolAddress((void**)&qr, g_qr);
    cudaGetSymbolAddress((void**)&kr, g_kr);
    cudaGetSymbolAddress((void**)&vt, g_vt);
    cudaGetSymbolAddress((void**)&ao, g_ao);
    cudaGetSymbolAddress((void**)&mb, g_mb);

    cudaFuncSetAttribute(proj_all, cudaFuncAttributeMaxDynamicSharedMemorySize, GSMEM);
    cudaFuncSetAttribute(tgemm_o,  cudaFuncAttributeMaxDynamicSharedMemorySize, GSMEM);
    cudaFuncSetAttribute(attn_mma_kernel, cudaFuncAttributeMaxDynamicSharedMemorySize, ATTN_SMEM);

    // Q/K/V projections in one launch
    proj_all<<<dim3(12, MM / TBM), 256, GSMEM>>>(hs, Wq, bq, Wk, bk, Wv, bv, q, k, v);

    // rope (q,k) + vtrans + mask bias in one launch
    {
        int ropeBlocks = (MM * (NH + NKV) * 32 + MM + 255) / 256;
        post_kernel<<<256 + ropeBlocks, 256>>>(q, qr, k, kr, v, vt, mask, mb);
    }

    // attention
    attn_mma_kernel<<<dim3(SS / BQ, NH, BB), 128, ATTN_SMEM>>>(qr, kr, vt, mb, ao);

    // output projection
    tgemm_o<<<dim3(DD / TBN, MM / TBM), 256, GSMEM>>>(ao, Wo, bo, out);
}